// round 6
// baseline (speedup 1.0000x reference)
#include <cuda_runtime.h>
#include <cstdint>

// ---------------- problem constants ----------------
#define NTOT   61440
#define NODES  30
#define BATCH  2048
#define INCH   12
#define EDGES  491520
#define C0     128
#define C1     512
#define C2     128
#define FCIN   (C2*NODES)     // 3840
#define FCOUT  72

#define NB_LIN ((NTOT+255)/256)    // 240
#define NB_DEG ((EDGES+255)/256)   // 1920

// ---------------- scratch ----------------
__device__ float g_h   [NTOT*INCH];          // [n][c]
__device__ float g_deg [NTOT];               // zero-init; re-zeroed by k_fc tail
__device__ float g_dinv[NTOT];
__device__ float g_A0  [NTOT*INCH];          // [n=(b,t)][c] GCN output
__device__ float g_X1  [(size_t)C0*NODES*BATCH];   // [c][t][b]
__device__ float g_X2  [(size_t)C1*NODES*BATCH];
__device__ float g_X3  [(size_t)C2*NODES*BATCH];

// ---------------- f32x2 helpers ----------------
typedef unsigned long long ull;
__device__ __forceinline__ ull dup2(float v) {
    ull r; asm("mov.b64 %0, {%1, %1};" : "=l"(r) : "f"(v)); return r;
}
__device__ __forceinline__ void unpack2(ull v, float& lo, float& hi) {
    asm("mov.b64 {%0, %1}, %2;" : "=f"(lo), "=f"(hi) : "l"(v));
}
__device__ __forceinline__ void fma2(ull& d, ull a, ull b) {
    asm("fma.rn.f32x2 %0, %1, %2, %0;" : "+l"(d) : "l"(a), "l"(b));
}

// ---------------- launch 1: GCN linear + degree count (independent halves) ----------------
__global__ void k_pre(const float* __restrict__ x, const float* __restrict__ w,
                      const int* __restrict__ dst) {
    int bid = blockIdx.x;
    if (bid < NB_LIN) {
        __shared__ float sw[INCH*INCH];
        if (threadIdx.x < INCH*INCH) sw[threadIdx.x] = w[threadIdx.x];
        __syncthreads();
        int n = bid*blockDim.x + threadIdx.x;
        if (n >= NTOT) return;
        float xr[INCH];
#pragma unroll
        for (int i = 0; i < INCH; i++) xr[i] = x[n*INCH + i];
#pragma unroll
        for (int c = 0; c < INCH; c++) {
            float s = 0.f;
#pragma unroll
            for (int i = 0; i < INCH; i++) s = fmaf(sw[c*INCH + i], xr[i], s);
            g_h[n*INCH + c] = s;
        }
    } else {
        int e = (bid - NB_LIN)*blockDim.x + threadIdx.x;
        if (e < EDGES) atomicAdd(&g_deg[dst[e]], 1.0f);   // g_deg starts at 0
    }
}

// ---------------- launch 2: dinv (+1 self-loop) + A0 init ----------------
__global__ void k_dinv_init(const float* __restrict__ gcn_b) {
    int n = blockIdx.x*blockDim.x + threadIdx.x;
    if (n >= NTOT) return;
    float di = rsqrtf(g_deg[n] + 1.0f);
    g_dinv[n] = di;
    float s = di*di;
#pragma unroll
    for (int c = 0; c < INCH; c++)
        g_A0[n*INCH + c] = fmaf(s, g_h[n*INCH + c], gcn_b[c]);
}

// ---------------- launch 3: edge scatter ----------------
__global__ void k_scatter(const int* __restrict__ src, const int* __restrict__ dst) {
    int id = blockIdx.x*blockDim.x + threadIdx.x;
    if (id >= EDGES*INCH) return;
    int e = id / INCH, c = id % INCH;
    int s = src[e], d = dst[e];
    float v = g_dinv[s]*g_dinv[d]*g_h[s*INCH + c];
    atomicAdd(&g_A0[d*INCH + c], v);
}

// ---------------- TCN GEMM body: 512 threads, thread tile 8 oc x 2 b ----------------
// out[oc][t][b]: acc1 = causal conv (taps at t-2D,t-D,t), acc2 = 1x1 down at t
// X = relu( relu(acc1+cb) + acc2+db )
// A0MODE: gather input from g_A0 [(b,t)][c]; else from Xin [c][t][b].
template<int IN, int OUT, int DIL, int BK, bool A0MODE>
__device__ __forceinline__ void tcn_gemm_body(
      const float* __restrict__ Xin, float* __restrict__ Xout,
      const float* __restrict__ cw, const float* __restrict__ cb,
      const float* __restrict__ dw, const float* __restrict__ db) {
    constexpr int BN = 64, BM = 128, NT = 512;
    __shared__ float A_s[BK*3*BN];       // [ic][k][b]
    __shared__ float B_s[BM*BK*8];       // [oc][ic][w0,w0,w1,w1,w2,w2,w3,w3]
    const int t   = blockIdx.x;
    const int b0  = blockIdx.y * BN;
    const int oc0 = blockIdx.z * BM;
    const int tid = threadIdx.x;
    const int tx = tid & 31, ty = tid >> 5;   // tx: b-lane (x2), ty: oc-row (x8)
    const int bb = tx*2, oct = ty*8;

    ull acc1[8], acc2[8];
#pragma unroll
    for (int j = 0; j < 8; j++) { acc1[j] = 0ULL; acc2[j] = 0ULL; }

    for (int ic0 = 0; ic0 < IN; ic0 += BK) {
        // stage A
        for (int i = tid; i < BK*3*BN; i += NT) {
            int ic = i/(3*BN); int r = i%(3*BN); int kk = r/BN; int b = r%BN;
            int tk = t + (kk-2)*DIL;
            float v = 0.f;
            if (tk >= 0) {
                if (A0MODE) v = Xin[((size_t)(b0+b)*NODES + tk)*INCH + ic0+ic];
                else        v = Xin[((size_t)(ic0+ic)*NODES + tk)*BATCH + b0 + b];
            }
            A_s[i] = v;
        }
        // stage B duplicated: one STS.64 per weight
        for (int i = tid; i < BM*BK*4; i += NT) {
            int oc = i/(BK*4); int r = i%(BK*4); int ic = r/4; int w = r&3;
            float v;
            if (w < 3) v = cw[((size_t)(oc0+oc)*IN + ic0+ic)*3 + w];
            else       v = dw[(size_t)(oc0+oc)*IN + ic0+ic];
            *reinterpret_cast<ull*>(&B_s[i*2]) = dup2(v);
        }
        __syncthreads();
#pragma unroll
        for (int ic = 0; ic < BK; ic++) {
            ull a0 = *reinterpret_cast<const ull*>(&A_s[(ic*3+0)*BN + bb]);
            ull a1 = *reinterpret_cast<const ull*>(&A_s[(ic*3+1)*BN + bb]);
            ull a2 = *reinterpret_cast<const ull*>(&A_s[(ic*3+2)*BN + bb]);
#pragma unroll
            for (int j = 0; j < 8; j++) {
                const float* wb = &B_s[((size_t)(oct+j)*BK + ic)*8];
                ulonglong2 wA = *reinterpret_cast<const ulonglong2*>(wb);     // w0,w1 dups
                ulonglong2 wB = *reinterpret_cast<const ulonglong2*>(wb+4);   // w2,w3 dups
                fma2(acc1[j], wA.x, a0);
                fma2(acc1[j], wA.y, a1);
                fma2(acc1[j], wB.x, a2);
                fma2(acc2[j], wB.y, a2);
            }
        }
        __syncthreads();
    }
    // epilogue
#pragma unroll
    for (int j = 0; j < 8; j++) {
        int oc = oc0 + oct + j;
        float cbv = cb[oc], dbv = db[oc];
        float c0,c1,d0,d1;
        unpack2(acc1[j], c0, c1);
        unpack2(acc2[j], d0, d1);
        float2 o;
        o.x = fmaxf(fmaxf(c0+cbv, 0.f) + d0 + dbv, 0.f);
        o.y = fmaxf(fmaxf(c1+cbv, 0.f) + d1 + dbv, 0.f);
        *reinterpret_cast<float2*>(&Xout[((size_t)oc*NODES + t)*BATCH + b0 + bb]) = o;
    }
}

__global__ void __launch_bounds__(512)
k_tcn0(const float* __restrict__ cw, const float* __restrict__ cb,
       const float* __restrict__ dw, const float* __restrict__ db) {
    tcn_gemm_body<INCH, C0, 1, 12, true>(g_A0, g_X1, cw, cb, dw, db);
}
__global__ void __launch_bounds__(512)
k_tcn1(const float* __restrict__ cw, const float* __restrict__ cb,
       const float* __restrict__ dw, const float* __restrict__ db) {
    tcn_gemm_body<C0, C1, 3, 8, false>(g_X1, g_X2, cw, cb, dw, db);
}
__global__ void __launch_bounds__(512)
k_tcn2(const float* __restrict__ cw, const float* __restrict__ cb,
       const float* __restrict__ dw, const float* __restrict__ db) {
    tcn_gemm_body<C1, C2, 9, 8, false>(g_X2, g_X3, cw, cb, dw, db);
}

// ---------------- FC: out[2048,72] = X3^T @ W^T + b ; tail re-zeroes g_deg ----------------
#define FC_BM 32
#define FC_BK 32
__global__ void __launch_bounds__(256)
k_fc(const float* __restrict__ W, const float* __restrict__ bias,
     float* __restrict__ out) {
    const float* T = g_X3;               // [k][b]
    __shared__ float Ts[FC_BK][FC_BM+1];
    __shared__ float Ws[80][FC_BK+1];
    int b0 = blockIdx.x * FC_BM;
    int tid = threadIdx.x;
    int tr = tid / 16;
    int tc = tid % 16;
    float acc[2][5] = {};
    for (int k0 = 0; k0 < FCIN; k0 += FC_BK) {
        for (int i = tid; i < FC_BK*FC_BM; i += 256) {
            int k = i / FC_BM, m = i % FC_BM;
            Ts[k][m] = T[(size_t)(k0+k)*BATCH + b0 + m];
        }
        for (int i = tid; i < 80*FC_BK; i += 256) {
            int n = i / FC_BK, k = i % FC_BK;
            Ws[n][k] = (n < FCOUT) ? W[(size_t)n*FCIN + k0 + k] : 0.f;
        }
        __syncthreads();
#pragma unroll
        for (int kk = 0; kk < FC_BK; kk++) {
            float a0 = Ts[kk][tr*2+0];
            float a1 = Ts[kk][tr*2+1];
#pragma unroll
            for (int j = 0; j < 5; j++) {
                float bv = Ws[tc*5+j][kk];
                acc[0][j] = fmaf(a0, bv, acc[0][j]);
                acc[1][j] = fmaf(a1, bv, acc[1][j]);
            }
        }
        __syncthreads();
    }
#pragma unroll
    for (int i = 0; i < 2; i++) {
        int b = b0 + tr*2 + i;
#pragma unroll
        for (int j = 0; j < 5; j++) {
            int o = tc*5 + j;
            if (o < FCOUT) out[(size_t)b*FCOUT + o] = acc[i][j] + bias[o];
        }
    }
    // re-zero degree buffer for the next kernel_launch invocation (stream-ordered)
    for (int i = blockIdx.x*256 + tid; i < NTOT; i += gridDim.x*256)
        g_deg[i] = 0.f;
}

// ---------------- launch (kernel launches ONLY; tcn0 is launch #4 for ncu) ----------------
extern "C" void kernel_launch(void* const* d_in, const int* in_sizes, int n_in,
                              void* d_out, int out_size) {
    const float* x     = (const float*)d_in[0];
    const int*   ei    = (const int*)d_in[1];
    const float* gcn_w = (const float*)d_in[2];
    const float* gcn_b = (const float*)d_in[3];
    const float* cw0   = (const float*)d_in[4];
    const float* cb0   = (const float*)d_in[5];
    const float* dw0   = (const float*)d_in[6];
    const float* db0   = (const float*)d_in[7];
    const float* cw1   = (const float*)d_in[8];
    const float* cb1   = (const float*)d_in[9];
    const float* dw1   = (const float*)d_in[10];
    const float* db1   = (const float*)d_in[11];
    const float* cw2   = (const float*)d_in[12];
    const float* cb2   = (const float*)d_in[13];
    const float* dw2   = (const float*)d_in[14];
    const float* db2   = (const float*)d_in[15];
    const float* fc_w  = (const float*)d_in[16];
    const float* fc_b  = (const float*)d_in[17];
    float* out = (float*)d_out;

    const int* src = ei;
    const int* dst = ei + EDGES;

    k_pre<<<NB_LIN + NB_DEG, 256>>>(x, gcn_w, dst);
    k_dinv_init<<<(NTOT+255)/256, 256>>>(gcn_b);
    k_scatter<<<(EDGES*INCH+255)/256, 256>>>(src, dst);

    k_tcn0<<<dim3(NODES, BATCH/64, 1), 512>>>(cw0, cb0, dw0, db0);
    k_tcn1<<<dim3(NODES, BATCH/64, C1/128), 512>>>(cw1, cb1, dw1, db1);
    k_tcn2<<<dim3(NODES, BATCH/64, 1), 512>>>(cw2, cb2, dw2, db2);

    k_fc<<<BATCH/FC_BM, 256>>>(fc_w, fc_b, out);
}

// round 7
// speedup vs baseline: 1.2807x; 1.2807x over previous
#include <cuda_runtime.h>
#include <cstdint>

// ---------------- problem constants ----------------
#define NTOT   61440
#define NODES  30
#define BATCH  2048
#define INCH   12
#define EDGES  491520
#define C0     128
#define C1     512
#define C2     128
#define FCIN   (C2*NODES)     // 3840
#define FCOUT  72

#define NB_LIN ((NTOT+255)/256)    // 240
#define NB_DEG ((EDGES+255)/256)   // 1920

// ---------------- scratch ----------------
__device__ float g_h   [NTOT*INCH];          // [n][c]
__device__ float g_deg [NTOT];               // zero-init; re-zeroed by k_fc tail
__device__ float g_dinv[NTOT];
__device__ float g_A0  [NTOT*INCH];          // [n=(b,t)][c] GCN output
__device__ float g_X1  [(size_t)C0*NODES*BATCH];   // [c][t][b]
__device__ float g_X2  [(size_t)C1*NODES*BATCH];
__device__ float g_X3  [(size_t)C2*NODES*BATCH];

// ---------------- f32x2 helpers ----------------
typedef unsigned long long ull;
__device__ __forceinline__ ull dup2(float v) {
    ull r; asm("mov.b64 %0, {%1, %1};" : "=l"(r) : "f"(v)); return r;
}
__device__ __forceinline__ void unpack2(ull v, float& lo, float& hi) {
    asm("mov.b64 {%0, %1}, %2;" : "=f"(lo), "=f"(hi) : "l"(v));
}
__device__ __forceinline__ void fma2(ull& d, ull a, ull b) {
    asm("fma.rn.f32x2 %0, %1, %2, %0;" : "+l"(d) : "l"(a), "l"(b));
}

// ---------------- launch 1: GCN linear + degree count ----------------
__global__ void k_pre(const float* __restrict__ x, const float* __restrict__ w,
                      const int* __restrict__ dst) {
    int bid = blockIdx.x;
    if (bid < NB_LIN) {
        __shared__ float sw[INCH*INCH];
        if (threadIdx.x < INCH*INCH) sw[threadIdx.x] = w[threadIdx.x];
        __syncthreads();
        int n = bid*blockDim.x + threadIdx.x;
        if (n >= NTOT) return;
        float xr[INCH];
#pragma unroll
        for (int i = 0; i < INCH; i++) xr[i] = x[n*INCH + i];
#pragma unroll
        for (int c = 0; c < INCH; c++) {
            float s = 0.f;
#pragma unroll
            for (int i = 0; i < INCH; i++) s = fmaf(sw[c*INCH + i], xr[i], s);
            g_h[n*INCH + c] = s;
        }
    } else {
        int e = (bid - NB_LIN)*blockDim.x + threadIdx.x;
        if (e < EDGES) atomicAdd(&g_deg[dst[e]], 1.0f);
    }
}

// ---------------- launch 2: dinv (+1 self-loop) + A0 init ----------------
__global__ void k_dinv_init(const float* __restrict__ gcn_b) {
    int n = blockIdx.x*blockDim.x + threadIdx.x;
    if (n >= NTOT) return;
    float di = rsqrtf(g_deg[n] + 1.0f);
    g_dinv[n] = di;
    float s = di*di;
#pragma unroll
    for (int c = 0; c < INCH; c++)
        g_A0[n*INCH + c] = fmaf(s, g_h[n*INCH + c], gcn_b[c]);
}

// ---------------- launch 3: edge scatter ----------------
__global__ void k_scatter(const int* __restrict__ src, const int* __restrict__ dst) {
    int id = blockIdx.x*blockDim.x + threadIdx.x;
    if (id >= EDGES*INCH) return;
    int e = id / INCH, c = id % INCH;
    int s = src[e], d = dst[e];
    float v = g_dinv[s]*g_dinv[d]*g_h[s*INCH + c];
    atomicAdd(&g_A0[d*INCH + c], v);
}

// ---------------- TCN GEMM body: 256 threads, thread tile 8 oc x 4 b ----------------
// Block tile: BM=64 oc x BN=128 b at one t. acc1 = 3-tap causal conv, acc2 = 1x1 down.
// X = relu( relu(acc1+cb) + acc2+db )
template<int IN, int OUT, int DIL, int BK, bool A0MODE>
__device__ __forceinline__ void tcn_gemm_body(
      const float* __restrict__ Xin, float* __restrict__ Xout,
      const float* __restrict__ cw, const float* __restrict__ cb,
      const float* __restrict__ dw, const float* __restrict__ db) {
    constexpr int BN = 128, BM = 64, NT = 256;
    __shared__ __align__(16) float A_s[BK*3*BN];   // [ic][tap][b]
    __shared__ __align__(16) float B_s[BM*BK*8];   // [oc][ic][w0,w0,w1,w1,w2,w2,w3,w3]
    const int t   = blockIdx.x;
    const int b0  = blockIdx.y * BN;
    const int oc0 = blockIdx.z * BM;
    const int tid = threadIdx.x;
    const int tx = tid & 31, ty = tid >> 5;   // tx: b-lane (x4), ty: oc-row (x8)
    const int bb = tx*4, oct = ty*8;

    ull acc1[8][2], acc2[8][2];
#pragma unroll
    for (int j = 0; j < 8; j++) { acc1[j][0]=acc1[j][1]=acc2[j][0]=acc2[j][1]=0ULL; }

    for (int ic0 = 0; ic0 < IN; ic0 += BK) {
        // stage A (coalesced along b in non-A0 mode)
        for (int i = tid; i < BK*3*BN; i += NT) {
            int ic = i/(3*BN); int r = i%(3*BN); int kk = r/BN; int b = r%BN;
            int tk = t + (kk-2)*DIL;
            float v = 0.f;
            if (tk >= 0) {
                if (A0MODE) v = Xin[((size_t)(b0+b)*NODES + tk)*INCH + ic0+ic];
                else        v = Xin[((size_t)(ic0+ic)*NODES + tk)*BATCH + b0 + b];
            }
            A_s[i] = v;
        }
        // stage B duplicated (one STS.64 per weight)
        for (int i = tid; i < BM*BK*4; i += NT) {
            int oc = i/(BK*4); int r = i%(BK*4); int ic = r/4; int w = r&3;
            float v;
            if (w < 3) v = cw[((size_t)(oc0+oc)*IN + ic0+ic)*3 + w];
            else       v = dw[(size_t)(oc0+oc)*IN + ic0+ic];
            *reinterpret_cast<ull*>(&B_s[i*2]) = dup2(v);
        }
        __syncthreads();
#pragma unroll
        for (int ic = 0; ic < BK; ic++) {
            ulonglong2 a0 = *reinterpret_cast<const ulonglong2*>(&A_s[(ic*3+0)*BN + bb]);
            ulonglong2 a1 = *reinterpret_cast<const ulonglong2*>(&A_s[(ic*3+1)*BN + bb]);
            ulonglong2 a2 = *reinterpret_cast<const ulonglong2*>(&A_s[(ic*3+2)*BN + bb]);
#pragma unroll
            for (int j = 0; j < 8; j++) {
                const float* wb = &B_s[((oct+j)*BK + ic)*8];
                ulonglong2 wA = *reinterpret_cast<const ulonglong2*>(wb);     // w0d, w1d
                ulonglong2 wB = *reinterpret_cast<const ulonglong2*>(wb+4);   // w2d, w3d
                fma2(acc1[j][0], wA.x, a0.x); fma2(acc1[j][1], wA.x, a0.y);
                fma2(acc1[j][0], wA.y, a1.x); fma2(acc1[j][1], wA.y, a1.y);
                fma2(acc1[j][0], wB.x, a2.x); fma2(acc1[j][1], wB.x, a2.y);
                fma2(acc2[j][0], wB.y, a2.x); fma2(acc2[j][1], wB.y, a2.y);
            }
        }
        __syncthreads();
    }
    // epilogue
#pragma unroll
    for (int j = 0; j < 8; j++) {
        int oc = oc0 + oct + j;
        float cbv = cb[oc], dbv = db[oc];
        float c0,c1,c2,c3, d0,d1,d2,d3;
        unpack2(acc1[j][0], c0, c1); unpack2(acc1[j][1], c2, c3);
        unpack2(acc2[j][0], d0, d1); unpack2(acc2[j][1], d2, d3);
        float4 o;
        o.x = fmaxf(fmaxf(c0+cbv, 0.f) + d0 + dbv, 0.f);
        o.y = fmaxf(fmaxf(c1+cbv, 0.f) + d1 + dbv, 0.f);
        o.z = fmaxf(fmaxf(c2+cbv, 0.f) + d2 + dbv, 0.f);
        o.w = fmaxf(fmaxf(c3+cbv, 0.f) + d3 + dbv, 0.f);
        *reinterpret_cast<float4*>(&Xout[((size_t)oc*NODES + t)*BATCH + b0 + bb]) = o;
    }
}

__global__ void __launch_bounds__(256, 2)
k_tcn0(const float* __restrict__ cw, const float* __restrict__ cb,
       const float* __restrict__ dw, const float* __restrict__ db) {
    tcn_gemm_body<INCH, C0, 1, 12, true>(g_A0, g_X1, cw, cb, dw, db);
}
__global__ void __launch_bounds__(256, 2)
k_tcn1(const float* __restrict__ cw, const float* __restrict__ cb,
       const float* __restrict__ dw, const float* __restrict__ db) {
    tcn_gemm_body<C0, C1, 3, 8, false>(g_X1, g_X2, cw, cb, dw, db);
}
__global__ void __launch_bounds__(256, 2)
k_tcn2(const float* __restrict__ cw, const float* __restrict__ cb,
       const float* __restrict__ dw, const float* __restrict__ db) {
    tcn_gemm_body<C1, C2, 9, 8, false>(g_X2, g_X3, cw, cb, dw, db);
}

// ---------------- FC: out[2048,72] = X3^T @ W^T + b ; tail re-zeroes g_deg ----------------
#define FC_BM 32
#define FC_BK 32
__global__ void __launch_bounds__(256)
k_fc(const float* __restrict__ W, const float* __restrict__ bias,
     float* __restrict__ out) {
    const float* T = g_X3;               // [k][b]
    __shared__ float Ts[FC_BK][FC_BM+1];
    __shared__ float Ws[80][FC_BK+1];
    int b0 = blockIdx.x * FC_BM;
    int tid = threadIdx.x;
    int tr = tid / 16;
    int tc = tid % 16;
    float acc[2][5] = {};
    for (int k0 = 0; k0 < FCIN; k0 += FC_BK) {
        for (int i = tid; i < FC_BK*FC_BM; i += 256) {
            int k = i / FC_BM, m = i % FC_BM;
            Ts[k][m] = T[(size_t)(k0+k)*BATCH + b0 + m];
        }
        for (int i = tid; i < 80*FC_BK; i += 256) {
            int n = i / FC_BK, k = i % FC_BK;
            Ws[n][k] = (n < FCOUT) ? W[(size_t)n*FCIN + k0 + k] : 0.f;
        }
        __syncthreads();
#pragma unroll
        for (int kk = 0; kk < FC_BK; kk++) {
            float a0 = Ts[kk][tr*2+0];
            float a1 = Ts[kk][tr*2+1];
#pragma unroll
            for (int j = 0; j < 5; j++) {
                float bv = Ws[tc*5+j][kk];
                acc[0][j] = fmaf(a0, bv, acc[0][j]);
                acc[1][j] = fmaf(a1, bv, acc[1][j]);
            }
        }
        __syncthreads();
    }
#pragma unroll
    for (int i = 0; i < 2; i++) {
        int b = b0 + tr*2 + i;
#pragma unroll
        for (int j = 0; j < 5; j++) {
            int o = tc*5 + j;
            if (o < FCOUT) out[(size_t)b*FCOUT + o] = acc[i][j] + bias[o];
        }
    }
    // re-zero degree buffer for the next kernel_launch invocation (stream-ordered)
    for (int i = blockIdx.x*256 + tid; i < NTOT; i += gridDim.x*256)
        g_deg[i] = 0.f;
}

// ---------------- launch (kernel launches ONLY; tcn0 is launch #4 for ncu) ----------------
extern "C" void kernel_launch(void* const* d_in, const int* in_sizes, int n_in,
                              void* d_out, int out_size) {
    const float* x     = (const float*)d_in[0];
    const int*   ei    = (const int*)d_in[1];
    const float* gcn_w = (const float*)d_in[2];
    const float* gcn_b = (const float*)d_in[3];
    const float* cw0   = (const float*)d_in[4];
    const float* cb0   = (const float*)d_in[5];
    const float* dw0   = (const float*)d_in[6];
    const float* db0   = (const float*)d_in[7];
    const float* cw1   = (const float*)d_in[8];
    const float* cb1   = (const float*)d_in[9];
    const float* dw1   = (const float*)d_in[10];
    const float* db1   = (const float*)d_in[11];
    const float* cw2   = (const float*)d_in[12];
    const float* cb2   = (const float*)d_in[13];
    const float* dw2   = (const float*)d_in[14];
    const float* db2   = (const float*)d_in[15];
    const float* fc_w  = (const float*)d_in[16];
    const float* fc_b  = (const float*)d_in[17];
    float* out = (float*)d_out;

    const int* src = ei;
    const int* dst = ei + EDGES;

    k_pre<<<NB_LIN + NB_DEG, 256>>>(x, gcn_w, dst);
    k_dinv_init<<<(NTOT+255)/256, 256>>>(gcn_b);
    k_scatter<<<(EDGES*INCH+255)/256, 256>>>(src, dst);

    // grid = t x (b-tiles of 128) x (oc-tiles of 64)
    k_tcn0<<<dim3(NODES, BATCH/128, C0/64), 256>>>(cw0, cb0, dw0, db0);
    k_tcn1<<<dim3(NODES, BATCH/128, C1/64), 256>>>(cw1, cb1, dw1, db1);
    k_tcn2<<<dim3(NODES, BATCH/128, C2/64), 256>>>(cw2, cb2, dw2, db2);

    k_fc<<<BATCH/FC_BM, 256>>>(fc_w, fc_b, out);
}

// round 8
// speedup vs baseline: 1.2922x; 1.0090x over previous
#include <cuda_runtime.h>
#include <cstdint>

// ---------------- problem constants ----------------
#define NTOT   61440
#define NODES  30
#define BATCH  2048
#define INCH   12
#define EDGES  491520
#define C0     128
#define C1     512
#define C2     128
#define FCIN   (C2*NODES)     // 3840
#define FCOUT  72

#define NB_LIN ((NTOT+255)/256)    // 240
#define NB_DEG ((EDGES+255)/256)   // 1920

// ---------------- scratch ----------------
__device__ float g_h   [NTOT*INCH];          // [n][c]
__device__ float g_deg [NTOT];               // zero-init; re-zeroed by k_fc tail
__device__ float g_dinv[NTOT];
__device__ float g_A0  [NTOT*INCH];          // [n=(b,t)][c] GCN output
__device__ float g_X1  [(size_t)C0*NODES*BATCH];   // [c][t][b]
__device__ float g_X2  [(size_t)C1*NODES*BATCH];
__device__ float g_X3  [(size_t)C2*NODES*BATCH];

// ---------------- f32x2 helpers ----------------
typedef unsigned long long ull;
__device__ __forceinline__ ull dup2(float v) {
    ull r; asm("mov.b64 %0, {%1, %1};" : "=l"(r) : "f"(v)); return r;
}
__device__ __forceinline__ void unpack2(ull v, float& lo, float& hi) {
    asm("mov.b64 {%0, %1}, %2;" : "=f"(lo), "=f"(hi) : "l"(v));
}
__device__ __forceinline__ void fma2(ull& d, ull a, ull b) {
    asm("fma.rn.f32x2 %0, %1, %2, %0;" : "+l"(d) : "l"(a), "l"(b));
}

// ---------------- launch 1: GCN linear + degree count ----------------
__global__ void k_pre(const float* __restrict__ x, const float* __restrict__ w,
                      const int* __restrict__ dst) {
    int bid = blockIdx.x;
    if (bid < NB_LIN) {
        __shared__ float sw[INCH*INCH];
        if (threadIdx.x < INCH*INCH) sw[threadIdx.x] = w[threadIdx.x];
        __syncthreads();
        int n = bid*blockDim.x + threadIdx.x;
        if (n >= NTOT) return;
        float xr[INCH];
#pragma unroll
        for (int i = 0; i < INCH; i++) xr[i] = x[n*INCH + i];
#pragma unroll
        for (int c = 0; c < INCH; c++) {
            float s = 0.f;
#pragma unroll
            for (int i = 0; i < INCH; i++) s = fmaf(sw[c*INCH + i], xr[i], s);
            g_h[n*INCH + c] = s;
        }
    } else {
        int e = (bid - NB_LIN)*blockDim.x + threadIdx.x;
        if (e < EDGES) atomicAdd(&g_deg[dst[e]], 1.0f);
    }
}

// ---------------- launch 2: dinv (+1 self-loop) + A0 init ----------------
__global__ void k_dinv_init(const float* __restrict__ gcn_b) {
    int n = blockIdx.x*blockDim.x + threadIdx.x;
    if (n >= NTOT) return;
    float di = rsqrtf(g_deg[n] + 1.0f);
    g_dinv[n] = di;
    float s = di*di;
#pragma unroll
    for (int c = 0; c < INCH; c++)
        g_A0[n*INCH + c] = fmaf(s, g_h[n*INCH + c], gcn_b[c]);
}

// ---------------- launch 3: edge scatter ----------------
__global__ void k_scatter(const int* __restrict__ src, const int* __restrict__ dst) {
    int id = blockIdx.x*blockDim.x + threadIdx.x;
    if (id >= EDGES*INCH) return;
    int e = id / INCH, c = id % INCH;
    int s = src[e], d = dst[e];
    float v = g_dinv[s]*g_dinv[d]*g_h[s*INCH + c];
    atomicAdd(&g_A0[d*INCH + c], v);
}

// ---------------- TCN GEMM body: 256 threads, thread tile 8 oc x 4 b ----------------
// Block tile: BM=64 oc x BN=128 b at one t. acc1 = 3-tap causal conv, acc2 = 1x1 down.
// X = relu( relu(acc1+cb) + acc2+db )
template<int IN, int OUT, int DIL, int BK, bool A0MODE>
__device__ __forceinline__ void tcn_gemm_body(
      const float* __restrict__ Xin, float* __restrict__ Xout,
      const float* __restrict__ cw, const float* __restrict__ cb,
      const float* __restrict__ dw, const float* __restrict__ db) {
    constexpr int BN = 128, BM = 64, NT = 256;
    __shared__ __align__(16) float A_s[BK*3*BN];   // [ic][tap][b]
    __shared__ __align__(16) float B_s[BM*BK*8];   // [oc][ic][w0,w0,w1,w1,w2,w2,w3,w3]
    const int t   = blockIdx.x;
    const int b0  = blockIdx.y * BN;
    const int oc0 = blockIdx.z * BM;
    const int tid = threadIdx.x;
    const int tx = tid & 31, ty = tid >> 5;   // tx: b-lane (x4), ty: oc-row (x8)
    const int bb = tx*4, oct = ty*8;

    ull acc1[8][2], acc2[8][2];
#pragma unroll
    for (int j = 0; j < 8; j++) { acc1[j][0]=acc1[j][1]=acc2[j][0]=acc2[j][1]=0ULL; }

    for (int ic0 = 0; ic0 < IN; ic0 += BK) {
        // stage A (coalesced along b in non-A0 mode)
        for (int i = tid; i < BK*3*BN; i += NT) {
            int ic = i/(3*BN); int r = i%(3*BN); int kk = r/BN; int b = r%BN;
            int tk = t + (kk-2)*DIL;
            float v = 0.f;
            if (tk >= 0) {
                if (A0MODE) v = Xin[((size_t)(b0+b)*NODES + tk)*INCH + ic0+ic];
                else        v = Xin[((size_t)(ic0+ic)*NODES + tk)*BATCH + b0 + b];
            }
            A_s[i] = v;
        }
        // stage B duplicated (one STS.64 per weight)
        for (int i = tid; i < BM*BK*4; i += NT) {
            int oc = i/(BK*4); int r = i%(BK*4); int ic = r/4; int w = r&3;
            float v;
            if (w < 3) v = cw[((size_t)(oc0+oc)*IN + ic0+ic)*3 + w];
            else       v = dw[(size_t)(oc0+oc)*IN + ic0+ic];
            *reinterpret_cast<ull*>(&B_s[i*2]) = dup2(v);
        }
        __syncthreads();
#pragma unroll
        for (int ic = 0; ic < BK; ic++) {
            ulonglong2 a0 = *reinterpret_cast<const ulonglong2*>(&A_s[(ic*3+0)*BN + bb]);
            ulonglong2 a1 = *reinterpret_cast<const ulonglong2*>(&A_s[(ic*3+1)*BN + bb]);
            ulonglong2 a2 = *reinterpret_cast<const ulonglong2*>(&A_s[(ic*3+2)*BN + bb]);
#pragma unroll
            for (int j = 0; j < 8; j++) {
                const float* wb = &B_s[((oct+j)*BK + ic)*8];
                ulonglong2 wA = *reinterpret_cast<const ulonglong2*>(wb);     // w0d, w1d
                ulonglong2 wB = *reinterpret_cast<const ulonglong2*>(wb+4);   // w2d, w3d
                fma2(acc1[j][0], wA.x, a0.x); fma2(acc1[j][1], wA.x, a0.y);
                fma2(acc1[j][0], wA.y, a1.x); fma2(acc1[j][1], wA.y, a1.y);
                fma2(acc1[j][0], wB.x, a2.x); fma2(acc1[j][1], wB.x, a2.y);
                fma2(acc2[j][0], wB.y, a2.x); fma2(acc2[j][1], wB.y, a2.y);
            }
        }
        __syncthreads();
    }
    // epilogue
#pragma unroll
    for (int j = 0; j < 8; j++) {
        int oc = oc0 + oct + j;
        float cbv = cb[oc], dbv = db[oc];
        float c0,c1,c2,c3, d0,d1,d2,d3;
        unpack2(acc1[j][0], c0, c1); unpack2(acc1[j][1], c2, c3);
        unpack2(acc2[j][0], d0, d1); unpack2(acc2[j][1], d2, d3);
        float4 o;
        o.x = fmaxf(fmaxf(c0+cbv, 0.f) + d0 + dbv, 0.f);
        o.y = fmaxf(fmaxf(c1+cbv, 0.f) + d1 + dbv, 0.f);
        o.z = fmaxf(fmaxf(c2+cbv, 0.f) + d2 + dbv, 0.f);
        o.w = fmaxf(fmaxf(c3+cbv, 0.f) + d3 + dbv, 0.f);
        *reinterpret_cast<float4*>(&Xout[((size_t)oc*NODES + t)*BATCH + b0 + bb]) = o;
    }
}

__global__ void __launch_bounds__(256, 2)
k_tcn0(const float* __restrict__ cw, const float* __restrict__ cb,
       const float* __restrict__ dw, const float* __restrict__ db) {
    tcn_gemm_body<INCH, C0, 1, 12, true>(g_A0, g_X1, cw, cb, dw, db);
}
__global__ void __launch_bounds__(256, 2)
k_tcn1(const float* __restrict__ cw, const float* __restrict__ cb,
       const float* __restrict__ dw, const float* __restrict__ db) {
    tcn_gemm_body<C0, C1, 3, 8, false>(g_X1, g_X2, cw, cb, dw, db);
}
__global__ void __launch_bounds__(256, 2)
k_tcn2(const float* __restrict__ cw, const float* __restrict__ cb,
       const float* __restrict__ dw, const float* __restrict__ db) {
    tcn_gemm_body<C1, C2, 9, 8, false>(g_X2, g_X3, cw, cb, dw, db);
}

// ---------------- FC: out[2048,72] = X3^T @ W^T + b ; tail re-zeroes g_deg ----------------
#define FC_BM 32
#define FC_BK 32
__global__ void __launch_bounds__(256)
k_fc(const float* __restrict__ W, const float* __restrict__ bias,
     float* __restrict__ out) {
    const float* T = g_X3;               // [k][b]
    __shared__ float Ts[FC_BK][FC_BM+1];
    __shared__ float Ws[80][FC_BK+1];
    int b0 = blockIdx.x * FC_BM;
    int tid = threadIdx.x;
    int tr = tid / 16;
    int tc = tid % 16;
    float acc[2][5] = {};
    for (int k0 = 0; k0 < FCIN; k0 += FC_BK) {
        for (int i = tid; i < FC_BK*FC_BM; i += 256) {
            int k = i / FC_BM, m = i % FC_BM;
            Ts[k][m] = T[(size_t)(k0+k)*BATCH + b0 + m];
        }
        for (int i = tid; i < 80*FC_BK; i += 256) {
            int n = i / FC_BK, k = i % FC_BK;
            Ws[n][k] = (n < FCOUT) ? W[(size_t)n*FCIN + k0 + k] : 0.f;
        }
        __syncthreads();
#pragma unroll
        for (int kk = 0; kk < FC_BK; kk++) {
            float a0 = Ts[kk][tr*2+0];
            float a1 = Ts[kk][tr*2+1];
#pragma unroll
            for (int j = 0; j < 5; j++) {
                float bv = Ws[tc*5+j][kk];
                acc[0][j] = fmaf(a0, bv, acc[0][j]);
                acc[1][j] = fmaf(a1, bv, acc[1][j]);
            }
        }
        __syncthreads();
    }
#pragma unroll
    for (int i = 0; i < 2; i++) {
        int b = b0 + tr*2 + i;
#pragma unroll
        for (int j = 0; j < 5; j++) {
            int o = tc*5 + j;
            if (o < FCOUT) out[(size_t)b*FCOUT + o] = acc[i][j] + bias[o];
        }
    }
    // re-zero degree buffer for the next kernel_launch invocation (stream-ordered)
    for (int i = blockIdx.x*256 + tid; i < NTOT; i += gridDim.x*256)
        g_deg[i] = 0.f;
}

// ---------------- launch (kernel launches ONLY; tcn0 is launch #4 for ncu) ----------------
extern "C" void kernel_launch(void* const* d_in, const int* in_sizes, int n_in,
                              void* d_out, int out_size) {
    const float* x     = (const float*)d_in[0];
    const int*   ei    = (const int*)d_in[1];
    const float* gcn_w = (const float*)d_in[2];
    const float* gcn_b = (const float*)d_in[3];
    const float* cw0   = (const float*)d_in[4];
    const float* cb0   = (const float*)d_in[5];
    const float* dw0   = (const float*)d_in[6];
    const float* db0   = (const float*)d_in[7];
    const float* cw1   = (const float*)d_in[8];
    const float* cb1   = (const float*)d_in[9];
    const float* dw1   = (const float*)d_in[10];
    const float* db1   = (const float*)d_in[11];
    const float* cw2   = (const float*)d_in[12];
    const float* cb2   = (const float*)d_in[13];
    const float* dw2   = (const float*)d_in[14];
    const float* db2   = (const float*)d_in[15];
    const float* fc_w  = (const float*)d_in[16];
    const float* fc_b  = (const float*)d_in[17];
    float* out = (float*)d_out;

    const int* src = ei;
    const int* dst = ei + EDGES;

    k_pre<<<NB_LIN + NB_DEG, 256>>>(x, gcn_w, dst);
    k_dinv_init<<<(NTOT+255)/256, 256>>>(gcn_b);
    k_scatter<<<(EDGES*INCH+255)/256, 256>>>(src, dst);

    // grid = t x (b-tiles of 128) x (oc-tiles of 64)
    k_tcn0<<<dim3(NODES, BATCH/128, C0/64), 256>>>(cw0, cb0, dw0, db0);
    k_tcn1<<<dim3(NODES, BATCH/128, C1/64), 256>>>(cw1, cb1, dw1, db1);
    k_tcn2<<<dim3(NODES, BATCH/128, C2/64), 256>>>(cw2, cb2, dw2, db2);

    k_fc<<<BATCH/FC_BM, 256>>>(fc_w, fc_b, out);
}